// round 3
// baseline (speedup 1.0000x reference)
#include <cuda_runtime.h>
#include <math.h>

// ---------------- problem constants ----------------
#define BGR   128
#define NAT   32
#define NODES 4096
#define HID   256
#define TYPED 100
#define EDIM  66
#define NLAY  4
#define NBLK  2048          // edge blocks (2 nodes each)

// ---------------- scratch (device globals) ----------------
__device__ float g_feat[NODES * 384];
__device__ float g_nf  [NODES * HID];
__device__ float g_h   [NODES * HID];
__device__ float g_P   [NODES * 512];         // [:,0:256]=Pi(+bias), [:,256:512]=Pj
__device__ float g_msg [NODES * HID];
__device__ float g_act [NODES * HID];
__device__ float g_gf  [BGR * HID];
__device__ float g_ef  [(size_t)NBLK * EDIM * 64];   // [blk][66][64] transposed tiles

typedef unsigned long long ull;

__device__ __forceinline__ float silu_f(float x) { return x / (1.0f + __expf(-x)); }

// ---- f32x2 packed-FMA helpers (sm_103a FFMA2 path) ----
__device__ __forceinline__ ull pack_dup(float f) {
    ull r; asm("mov.b64 %0, {%1,%1};" : "=l"(r) : "f"(f)); return r;
}
__device__ __forceinline__ void unpack2(ull v, float& lo, float& hi) {
    asm("mov.b64 {%0,%1}, %2;" : "=f"(lo), "=f"(hi) : "l"(v));
}
__device__ __forceinline__ void fma2(ull& acc, ull a, ull b) {
    asm("fma.rn.f32x2 %0, %1, %2, %0;" : "+l"(acc) : "l"(a), "l"(b));
}

// ---- cp.async helpers ----
__device__ __forceinline__ void cp16(void* sdst, const void* gsrc) {
    unsigned s = (unsigned)__cvta_generic_to_shared(sdst);
    asm volatile("cp.async.cg.shared.global [%0], [%1], 16;" :: "r"(s), "l"(gsrc));
}
__device__ __forceinline__ void cp_commit() { asm volatile("cp.async.commit_group;"); }
template<int N> __device__ __forceinline__ void cp_wait() {
    asm volatile("cp.async.wait_group %0;" :: "n"(N));
}

// ---------------- generic fp32 GEMM (FFMA2 inner loop) ----------------
// C[M,N](ldc) = epilogue( A0[:,0:K0]@W[0:K0,:] + A1[:,0:K1]@W[K0:,:] + bias )
// mode 0: C = v ; mode 1: C = silu(v) ; mode 2: C += silu(v)
#define GBM 64
#define GBN 64
#define GBK 16
__global__ void __launch_bounds__(256) gemm_kernel(
    const float* __restrict__ A0, int K0,
    const float* __restrict__ A1, int K1,
    const float* __restrict__ W, int ldw,
    const float* __restrict__ bias,
    float* __restrict__ C, int ldc,
    int M, int N, int mode)
{
    __shared__ float As[GBK][GBM + 2];
    __shared__ float Wsm[GBK][GBN];
    const int tid = threadIdx.x;
    const int tx = tid & 15;          // 16 col groups (4 cols each)
    const int ty = tid >> 4;          // 16 row groups (4 rows each)
    const int row0 = blockIdx.x * GBM;
    const int col0 = blockIdx.y * GBN;
    const int K = K0 + K1;

    ull acc2[2][4];
    #pragma unroll
    for (int i = 0; i < 2; i++)
        #pragma unroll
        for (int j = 0; j < 4; j++) acc2[i][j] = 0ULL;

    for (int kt = 0; kt < K; kt += GBK) {
        {   // load A tile (64 x 16)
            const int m  = tid >> 2;
            const int kb = (tid & 3) * 4;
            const int gr = row0 + m;
            #pragma unroll
            for (int i = 0; i < 4; i++) {
                const int k  = kb + i;
                const int gk = kt + k;
                float v = 0.0f;
                if (gk < K) {
                    if (gk < K0) v = A0[(size_t)gr * K0 + gk];
                    else         v = A1[(size_t)gr * K1 + (gk - K0)];
                }
                As[k][m] = v;
            }
        }
        #pragma unroll
        for (int i = 0; i < 4; i++) {   // load W tile (16 x 64)
            const int idx = tid + 256 * i;
            const int k = idx >> 6;
            const int n = idx & 63;
            const int gk = kt + k;
            const int gn = col0 + n;
            Wsm[k][n] = (gk < K && gn < N) ? W[(size_t)gk * ldw + gn] : 0.0f;
        }
        __syncthreads();
        #pragma unroll
        for (int k = 0; k < GBK; k++) {
            const ull a0 = *(const ull*)&As[k][ty * 4];
            const ull a1 = *(const ull*)&As[k][ty * 4 + 2];
            const float4 w4 = *(const float4*)&Wsm[k][tx * 4];
            ull wd[4];
            wd[0] = pack_dup(w4.x); wd[1] = pack_dup(w4.y);
            wd[2] = pack_dup(w4.z); wd[3] = pack_dup(w4.w);
            #pragma unroll
            for (int j = 0; j < 4; j++) { fma2(acc2[0][j], a0, wd[j]); fma2(acc2[1][j], a1, wd[j]); }
        }
        __syncthreads();
    }

    #pragma unroll
    for (int i2 = 0; i2 < 2; i2++) {
        #pragma unroll
        for (int j = 0; j < 4; j++) {
            float lo, hi; unpack2(acc2[i2][j], lo, hi);
            const int c = col0 + tx * 4 + j;
            if (c >= N) continue;
            const int ra = row0 + ty * 4 + 2 * i2;
            float pair[2] = {lo, hi};
            #pragma unroll
            for (int u = 0; u < 2; u++) {
                const int r = ra + u;
                if (r >= M) continue;
                float v = pair[u];
                if (bias) v += bias[c];
                if (mode == 1)      v = silu_f(v);
                else if (mode == 2) v = C[(size_t)r * ldc + c] + silu_f(v);
                C[(size_t)r * ldc + c] = v;
            }
        }
    }
}

// ---------------- time embedding -> feat[:,256:384] ----------------
__global__ void timefeat_kernel(const float* __restrict__ t, float* __restrict__ feat)
{
    const int idx = blockIdx.x * blockDim.x + threadIdx.x;
    if (idx >= NODES * 128) return;
    const int node = idx >> 7;
    const int c = idx & 127;
    const int b = node >> 5;
    const float tv = t[b];
    const float kfac = -logf(10000.0f) / 63.0f;
    float val;
    if (c < 64) val = sinf(tv * __expf((float)c * kfac));
    else        val = cosf(tv * __expf((float)(c - 64) * kfac));
    feat[(size_t)node * 384 + 256 + c] = val;
}

// ---------------- edge features, transposed per-block tiles ----------------
// layout: eft[bl][k(66)][r(64)], node = 2*bl + (r>>5), j = r&31
__global__ void edgefeat_kernel(const float* __restrict__ frac,
                                const float* __restrict__ lpolar,
                                float* __restrict__ eft)
{
    const int TOT = NBLK * EDIM * 64;
    int idx = blockIdx.x * blockDim.x + threadIdx.x;
    if (idx >= TOT) return;
    const int bl = idx / (EDIM * 64);
    const int rem = idx - bl * (EDIM * 64);
    const int k = rem >> 6;
    const int r = rem & 63;
    const int node = (bl << 1) + (r >> 5);
    const int j = r & 31;
    const int b = node >> 5;

    float val;
    if (k < 60) {
        const int cc  = (k < 30) ? k : (k - 30);
        const int dim = cc / 10;
        const int f   = cc - dim * 10;
        float d = frac[(b * 32 + j) * 3 + dim] - frac[node * 3 + dim];
        d -= floorf(d);
        const float arg = d * (6.283185307179586f * (float)f);
        val = (k < 30) ? sinf(arg) : cosf(arg);
    } else {
        val = lpolar[b * 6 + (k - 60)];
    }
    eft[idx] = val;
}

// ---------------- layernorm ----------------
__global__ void layernorm_kernel(const float* __restrict__ x,
                                 const float* __restrict__ g,
                                 const float* __restrict__ b,
                                 float* __restrict__ y)
{
    const int row = blockIdx.x;
    const int tid = threadIdx.x;
    const float v = x[(size_t)row * HID + tid];
    __shared__ float sred[8];

    float s = v;
    #pragma unroll
    for (int o = 16; o; o >>= 1) s += __shfl_xor_sync(0xffffffffu, s, o);
    if ((tid & 31) == 0) sred[tid >> 5] = s;
    __syncthreads();
    float tot = 0.0f;
    #pragma unroll
    for (int i = 0; i < 8; i++) tot += sred[i];
    const float mean = tot * (1.0f / 256.0f);
    const float d = v - mean;
    __syncthreads();

    float q = d * d;
    #pragma unroll
    for (int o = 16; o; o >>= 1) q += __shfl_xor_sync(0xffffffffu, q, o);
    if ((tid & 31) == 0) sred[tid >> 5] = q;
    __syncthreads();
    tot = 0.0f;
    #pragma unroll
    for (int i = 0; i < 8; i++) tot += sred[i];
    const float var = tot * (1.0f / 256.0f);

    y[(size_t)row * HID + tid] = d * rsqrtf(var + 1e-5f) * g[tid] + b[tid];
}

// ---------------- fused edge-message kernel (2 nodes / block) ----------------
// phase0: E = ef(64x66) @ W1c(66x256); X = silu(E + Pi + Pj)  -> XsT smem
// phase2: Y = X @ W2 (cp.async double-buffered); epilogue silu + mean over 32 j
#define XPAD 68
__global__ void __launch_bounds__(256, 1) edge_msg_kernel(
    const float* __restrict__ P,
    const float* __restrict__ eft,
    const float* __restrict__ W1c,
    const float* __restrict__ W2,
    const float* __restrict__ b2,
    float* __restrict__ msg)
{
    extern __shared__ float smx[];
    float* XsT  = smx;                   // [256][68]
    float* W1s  = XsT + 256 * XPAD;      // [66][256]
    float* W2b0 = W1s + EDIM * 256;      // [32][256]
    float* W2b1 = W2b0 + 32 * 256;       // [32][256]
    float* efs  = W2b1 + 32 * 256;       // [66][64]; aliased with red[8][256]
    float* red  = efs;

    const int bl = blockIdx.x;
    const int node0 = bl << 1;
    const int gb = node0 >> 5;
    const int tid = threadIdx.x;
    const int tx = tid & 31;             // col group: cols {4tx+q, 128+4tx+q}
    const int ty = tid >> 5;             // row group: rows ty*8 .. ty*8+7

    // ---- prefetch: G0 = ef + W1c, G1 = W2 chunk0, G2 = W2 chunk1 ----
    {
        const float4* g = (const float4*)(eft + (size_t)bl * (EDIM * 64));
        for (int i = tid; i < EDIM * 16; i += 256) cp16(((float4*)efs) + i, g + i);
        const float4* gw = (const float4*)W1c;
        for (int i = tid; i < EDIM * 64; i += 256) cp16(((float4*)W1s) + i, gw + i);
    }
    cp_commit();
    {
        const float4* gw = (const float4*)W2;
        #pragma unroll
        for (int q = 0; q < 8; q++) cp16(((float4*)W2b0) + tid + 256 * q, gw + tid + 256 * q);
        cp_commit();
        gw += 2048;
        #pragma unroll
        for (int q = 0; q < 8; q++) cp16(((float4*)W2b1) + tid + 256 * q, gw + tid + 256 * q);
        cp_commit();
    }

    cp_wait<2>();          // ef + W1c ready
    __syncthreads();

    // ---- phase 0: E = ef @ W1c, 8x8 tile/thread, row-paired f32x2 accs ----
    ull acc[4][8];
    #pragma unroll
    for (int p = 0; p < 4; p++)
        #pragma unroll
        for (int c = 0; c < 8; c++) acc[p][c] = 0ULL;

    #pragma unroll 2
    for (int k = 0; k < EDIM; k++) {
        ull ap[4];
        #pragma unroll
        for (int p = 0; p < 4; p++)
            ap[p] = *(const ull*)(efs + k * 64 + ty * 8 + 2 * p);
        const float4 wa = *(const float4*)(W1s + k * 256 + 4 * tx);
        const float4 wb = *(const float4*)(W1s + k * 256 + 128 + 4 * tx);
        ull wd[8];
        wd[0] = pack_dup(wa.x); wd[1] = pack_dup(wa.y); wd[2] = pack_dup(wa.z); wd[3] = pack_dup(wa.w);
        wd[4] = pack_dup(wb.x); wd[5] = pack_dup(wb.y); wd[6] = pack_dup(wb.z); wd[7] = pack_dup(wb.w);
        #pragma unroll
        for (int p = 0; p < 4; p++)
            #pragma unroll
            for (int c = 0; c < 8; c++) fma2(acc[p][c], ap[p], wd[c]);
    }

    // ---- phase 1: X = silu(E + Pi + Pj) -> XsT[col][row] ----
    {
        const int node = node0 + (ty >> 2);
        float pi[8];
        *(float4*)pi       = *(const float4*)(P + (size_t)node * 512 + 4 * tx);
        *(float4*)(pi + 4) = *(const float4*)(P + (size_t)node * 512 + 128 + 4 * tx);
        #pragma unroll
        for (int p = 0; p < 4; p++) {
            const int r0 = ty * 8 + 2 * p;
            const int j0 = r0 & 31;     // even, j0+1 stays in-graph
            const float* pjb0 = P + (size_t)(gb * 32 + j0) * 512 + 256;
            const float* pjb1 = pjb0 + 512;
            float pj0[8], pj1[8];
            *(float4*)pj0       = *(const float4*)(pjb0 + 4 * tx);
            *(float4*)(pj0 + 4) = *(const float4*)(pjb0 + 128 + 4 * tx);
            *(float4*)pj1       = *(const float4*)(pjb1 + 4 * tx);
            *(float4*)(pj1 + 4) = *(const float4*)(pjb1 + 128 + 4 * tx);
            #pragma unroll
            for (int c = 0; c < 8; c++) {
                float e0, e1; unpack2(acc[p][c], e0, e1);
                const int col = ((c >> 2) << 7) + 4 * tx + (c & 3);
                XsT[col * XPAD + r0]     = silu_f(e0 + pi[c] + pj0[c]);
                XsT[col * XPAD + r0 + 1] = silu_f(e1 + pi[c] + pj1[c]);
            }
        }
    }
    __syncthreads();

    // ---- phase 2: Y = X @ W2, 8 chunks of 32 k, double-buffered ----
    ull acc2[4][8];
    #pragma unroll
    for (int p = 0; p < 4; p++)
        #pragma unroll
        for (int c = 0; c < 8; c++) acc2[p][c] = 0ULL;

    #pragma unroll 1
    for (int ch = 0; ch < 8; ch++) {
        cp_wait<1>();
        __syncthreads();
        const float* Wb = (ch & 1) ? W2b1 : W2b0;
        const int kbase = ch * 32;
        #pragma unroll 2
        for (int kl = 0; kl < 32; kl++) {
            const int k = kbase + kl;
            ull ap[4];
            #pragma unroll
            for (int p = 0; p < 4; p++)
                ap[p] = *(const ull*)(XsT + k * XPAD + ty * 8 + 2 * p);
            const float4 wa = *(const float4*)(Wb + kl * 256 + 4 * tx);
            const float4 wb4 = *(const float4*)(Wb + kl * 256 + 128 + 4 * tx);
            ull wd[8];
            wd[0] = pack_dup(wa.x);  wd[1] = pack_dup(wa.y);  wd[2] = pack_dup(wa.z);  wd[3] = pack_dup(wa.w);
            wd[4] = pack_dup(wb4.x); wd[5] = pack_dup(wb4.y); wd[6] = pack_dup(wb4.z); wd[7] = pack_dup(wb4.w);
            #pragma unroll
            for (int p = 0; p < 4; p++)
                #pragma unroll
                for (int c = 0; c < 8; c++) fma2(acc2[p][c], ap[p], wd[c]);
        }
        __syncthreads();
        if (ch < 6) {
            const float4* gw = (const float4*)W2 + (size_t)(ch + 2) * 2048;
            float* dst = (ch & 1) ? W2b1 : W2b0;
            #pragma unroll
            for (int q = 0; q < 8; q++) cp16(((float4*)dst) + tid + 256 * q, gw + tid + 256 * q);
        }
        cp_commit();   // always commit to keep group accounting uniform
    }

    // ---- epilogue: bias + silu + mean over j, per node ----
    {
        float bb[8];
        *(float4*)bb       = *(const float4*)(b2 + 4 * tx);
        *(float4*)(bb + 4) = *(const float4*)(b2 + 128 + 4 * tx);
        float s[8];
        #pragma unroll
        for (int c = 0; c < 8; c++) s[c] = 0.0f;
        #pragma unroll
        for (int p = 0; p < 4; p++)
            #pragma unroll
            for (int c = 0; c < 8; c++) {
                float v0, v1; unpack2(acc2[p][c], v0, v1);
                s[c] += silu_f(v0 + bb[c]) + silu_f(v1 + bb[c]);
            }
        #pragma unroll
        for (int c = 0; c < 8; c++) {
            const int col = ((c >> 2) << 7) + 4 * tx + (c & 3);
            red[ty * 256 + col] = s[c];
        }
    }
    __syncthreads();
    {
        const int c = tid;
        const float m0 = red[c] + red[256 + c] + red[512 + c] + red[768 + c];
        const float m1 = red[1024 + c] + red[1280 + c] + red[1536 + c] + red[1792 + c];
        msg[(size_t)node0 * 256 + c]       = m0 * 0.03125f;
        msg[(size_t)(node0 + 1) * 256 + c] = m1 * 0.03125f;
    }
}

// ---------------- graph mean ----------------
__global__ void graphmean_kernel(const float* __restrict__ h, float* __restrict__ gf)
{
    const int b = blockIdx.x;
    const int c = threadIdx.x;
    float s = 0.0f;
    #pragma unroll
    for (int i = 0; i < 32; i++) s += h[(size_t)((b << 5) + i) * HID + c];
    gf[(size_t)b * HID + c] = s * (1.0f / 32.0f);
}

// ---------------- host launch ----------------
static void run_gemm(cudaStream_t s,
                     const float* A0, int K0, const float* A1, int K1,
                     const float* W, int ldw, const float* bias,
                     float* C, int ldc, int M, int N, int mode)
{
    dim3 grid((M + GBM - 1) / GBM, (N + GBN - 1) / GBN);
    gemm_kernel<<<grid, 256, 0, s>>>(A0, K0, A1, K1, W, ldw, bias, C, ldc, M, N, mode);
}

extern "C" void kernel_launch(void* const* d_in, const int* in_sizes, int n_in,
                              void* d_out, int out_size)
{
    const float* t          = (const float*)d_in[0];
    const float* atom_types = (const float*)d_in[1];
    const float* frac       = (const float*)d_in[2];
    const float* l_polar    = (const float*)d_in[3];
    const float* Ws      = (const float*)d_in[5];
    const float* bs      = (const float*)d_in[6];
    const float* Wn      = (const float*)d_in[7];
    const float* bn      = (const float*)d_in[8];
    const float* ln_g    = (const float*)d_in[9];
    const float* ln_b    = (const float*)d_in[10];
    const float* m1_W    = (const float*)d_in[11];
    const float* m1_b    = (const float*)d_in[12];
    const float* m2_W    = (const float*)d_in[13];
    const float* m2_b    = (const float*)d_in[14];
    const float* a1_W    = (const float*)d_in[15];
    const float* a1_b    = (const float*)d_in[16];
    const float* a2_W    = (const float*)d_in[17];
    const float* a2_b    = (const float*)d_in[18];
    const float* fln_g   = (const float*)d_in[19];
    const float* fln_b   = (const float*)d_in[20];
    const float* type_W  = (const float*)d_in[21];
    const float* type_b  = (const float*)d_in[22];
    const float* polar_W = (const float*)d_in[23];
    const float* frac_W  = (const float*)d_in[24];
    float* out = (float*)d_out;

    float *feat, *nf, *h, *P, *msg, *act, *gf, *ef;
    cudaGetSymbolAddress((void**)&feat, g_feat);
    cudaGetSymbolAddress((void**)&nf,   g_nf);
    cudaGetSymbolAddress((void**)&h,    g_h);
    cudaGetSymbolAddress((void**)&P,    g_P);
    cudaGetSymbolAddress((void**)&msg,  g_msg);
    cudaGetSymbolAddress((void**)&act,  g_act);
    cudaGetSymbolAddress((void**)&gf,   g_gf);
    cudaGetSymbolAddress((void**)&ef,   g_ef);

    const int EDGE_SMEM = (256 * XPAD + EDIM * 256 + 64 * 256 + EDIM * 64) * (int)sizeof(float);
    cudaFuncSetAttribute(edge_msg_kernel, cudaFuncAttributeMaxDynamicSharedMemorySize, EDGE_SMEM);

    cudaStream_t s = 0;

    // node features
    timefeat_kernel<<<(NODES * 128 + 255) / 256, 256, 0, s>>>(t, feat);
    run_gemm(s, atom_types, TYPED, nullptr, 0, Ws, HID, bs, feat, 384, NODES, HID, 0);
    run_gemm(s, feat, 384, nullptr, 0, Wn, HID, bn, nf, HID, NODES, HID, 0);

    // edge features (layer-independent), transposed tiles
    {
        const int TOT = NBLK * EDIM * 64;
        edgefeat_kernel<<<(TOT + 255) / 256, 256, 0, s>>>(frac, l_polar, ef);
    }

    for (int l = 0; l < NLAY; l++) {
        const float* W1 = m1_W + (size_t)l * 578 * HID;
        layernorm_kernel<<<NODES, 256, 0, s>>>(nf, ln_g + l * HID, ln_b + l * HID, h);
        // P[:,0:256] = h @ W1[0:256] + m1_b ; P[:,256:512] = h @ W1[256:512]
        run_gemm(s, h, HID, nullptr, 0, W1, HID, m1_b + l * HID, P, 512, NODES, HID, 0);
        run_gemm(s, h, HID, nullptr, 0, W1 + 256 * HID, HID, nullptr, P + 256, 512, NODES, HID, 0);
        // fused edge path
        edge_msg_kernel<<<NBLK, 256, EDGE_SMEM, s>>>(
            P, ef, W1 + 512 * HID, m2_W + (size_t)l * HID * HID, m2_b + l * HID, msg);
        // a = silu(concat(nf,msg) @ a1 + b)
        run_gemm(s, nf, HID, msg, HID, a1_W + (size_t)l * 512 * HID, HID,
                 a1_b + l * HID, act, HID, NODES, HID, 1);
        // nf += silu(a @ a2 + b)
        run_gemm(s, act, HID, nullptr, 0, a2_W + (size_t)l * HID * HID, HID,
                 a2_b + l * HID, nf, HID, NODES, HID, 2);
    }

    layernorm_kernel<<<NODES, 256, 0, s>>>(nf, fln_g, fln_b, h);
    graphmean_kernel<<<BGR, 256, 0, s>>>(h, gf);

    run_gemm(s, h, HID, nullptr, 0, type_W, TYPED, type_b, out, TYPED, NODES, TYPED, 0);
    run_gemm(s, gf, HID, nullptr, 0, polar_W, 6, nullptr,
             out + (size_t)NODES * TYPED, 6, BGR, 6, 0);
    run_gemm(s, h, HID, nullptr, 0, frac_W, 3, nullptr,
             out + (size_t)NODES * TYPED + (size_t)BGR * 6, 3, NODES, 3, 0);
}

// round 5
// speedup vs baseline: 1.2480x; 1.2480x over previous
#include <cuda_runtime.h>
#include <math.h>
#include <stdint.h>

#define BGR   128
#define NODES 4096
#define HID   256
#define TYPED 100
#define NLAY  4
#define NEBLK 1024

#if defined(__CUDA_ARCH_FEAT_SM103_ALL) || defined(__CUDA_ARCH_FEAT_SM100_ALL) || defined(__CUDA_ARCH_SPECIFIC__) || defined(__CUDA_ARCH_FAMILY_SPECIFIC__)
#define HAS_TC 1
#else
#define HAS_TC 0
#endif

__device__ float g_feat[NODES * 384];
__device__ float g_nf  [NODES * HID];
__device__ float g_h   [NODES * HID];
__device__ float g_P   [NODES * 512];
__device__ float g_PiQ [NODES * HID];
__device__ float g_PjT [BGR * HID * 32];
__device__ float g_msg [NODES * HID];
__device__ float g_act [NODES * HID];
__device__ float g_gf  [BGR * HID];
__device__ float g_efT [(size_t)NEBLK * 128 * 64];
__device__ float g_W1T [NLAY * 256 * 64];
__device__ float g_W2T [NLAY * 4 * 256 * 64];

typedef unsigned long long ull;

__device__ __forceinline__ float silu_f(float x) { return x / (1.0f + __expf(-x)); }
__device__ __forceinline__ ull pack_dup(float f) { ull r; asm("mov.b64 %0, {%1,%1};" : "=l"(r) : "f"(f)); return r; }
__device__ __forceinline__ void unpack2(ull v, float& lo, float& hi) { asm("mov.b64 {%0,%1}, %2;" : "=f"(lo), "=f"(hi) : "l"(v)); }
__device__ __forceinline__ void fma2(ull& a, ull x, ull y) { asm("fma.rn.f32x2 %0, %1, %2, %0;" : "+l"(a) : "l"(x), "l"(y)); }
__device__ __forceinline__ void cp16(void* sdst, const void* gsrc) {
    unsigned s = (unsigned)__cvta_generic_to_shared(sdst);
    asm volatile("cp.async.cg.shared.global [%0], [%1], 16;" :: "r"(s), "l"(gsrc));
}
__device__ __forceinline__ void cp_commit() { asm volatile("cp.async.commit_group;"); }
template<int N> __device__ __forceinline__ void cp_wait() { asm volatile("cp.async.wait_group %0;" :: "n"(N)); }
__device__ __forceinline__ uint32_t smu32(const void* p) { return (uint32_t)__cvta_generic_to_shared(p); }
__device__ __forceinline__ void mbar_init(uint32_t a, uint32_t c) {
    asm volatile("mbarrier.init.shared.b64 [%0], %1;" :: "r"(a), "r"(c) : "memory");
}
__device__ __forceinline__ void mbar_wait(uint32_t a, uint32_t ph) {
    asm volatile("{\n\t.reg .pred P;\nWL%=:\n\t"
        "mbarrier.try_wait.parity.acquire.cta.shared::cta.b64 P, [%0], %1, 0x989680;\n\t"
        "@!P bra WL%=;\n\t}" :: "r"(a), "r"(ph) : "memory");
}
__device__ __forceinline__ void fence_pa() { asm volatile("fence.proxy.async.shared::cta;" ::: "memory"); }
__device__ __forceinline__ uint32_t sw128(uint32_t b) { return b ^ ((b >> 3) & 0x70); }
__device__ __forceinline__ uint32_t tf32b(float v) { uint32_t o; asm("cvt.rna.tf32.f32 %0, %1;" : "=r"(o) : "f"(v)); return o; }

#if HAS_TC
__device__ __forceinline__ void tcf_b() { asm volatile("tcgen05.fence::before_thread_sync;" ::: "memory"); }
__device__ __forceinline__ void tcf_a() { asm volatile("tcgen05.fence::after_thread_sync;" ::: "memory"); }
__device__ __forceinline__ void tcw_ld() { asm volatile("tcgen05.wait::ld.sync.aligned;" ::: "memory"); }
__device__ __forceinline__ void tcw_st() { asm volatile("tcgen05.wait::st.sync.aligned;" ::: "memory"); }
__device__ __forceinline__ void tc_commit(uint32_t b) {
    asm volatile("tcgen05.commit.cta_group::1.mbarrier::arrive::one.shared::cluster.b64 [%0];" :: "r"(b) : "memory");
}
#define TC_LD_X32(r, a) \
    asm volatile("tcgen05.ld.sync.aligned.32x32b.x32.b32 " \
        "{%0,%1,%2,%3,%4,%5,%6,%7,%8,%9,%10,%11,%12,%13,%14,%15," \
        "%16,%17,%18,%19,%20,%21,%22,%23,%24,%25,%26,%27,%28,%29,%30,%31}, [%32];" \
        : "=r"((r)[0]),"=r"((r)[1]),"=r"((r)[2]),"=r"((r)[3]),"=r"((r)[4]),"=r"((r)[5]),"=r"((r)[6]),"=r"((r)[7]), \
          "=r"((r)[8]),"=r"((r)[9]),"=r"((r)[10]),"=r"((r)[11]),"=r"((r)[12]),"=r"((r)[13]),"=r"((r)[14]),"=r"((r)[15]), \
          "=r"((r)[16]),"=r"((r)[17]),"=r"((r)[18]),"=r"((r)[19]),"=r"((r)[20]),"=r"((r)[21]),"=r"((r)[22]),"=r"((r)[23]), \
          "=r"((r)[24]),"=r"((r)[25]),"=r"((r)[26]),"=r"((r)[27]),"=r"((r)[28]),"=r"((r)[29]),"=r"((r)[30]),"=r"((r)[31]) \
        : "r"(a))
#define TC_ST_X32(a, r) \
    asm volatile("tcgen05.st.sync.aligned.32x32b.x32.b32 [%0], " \
        "{%1,%2,%3,%4,%5,%6,%7,%8,%9,%10,%11,%12,%13,%14,%15,%16," \
        "%17,%18,%19,%20,%21,%22,%23,%24,%25,%26,%27,%28,%29,%30,%31,%32};" \
        :: "r"(a), \
           "r"((r)[0]),"r"((r)[1]),"r"((r)[2]),"r"((r)[3]),"r"((r)[4]),"r"((r)[5]),"r"((r)[6]),"r"((r)[7]), \
           "r"((r)[8]),"r"((r)[9]),"r"((r)[10]),"r"((r)[11]),"r"((r)[12]),"r"((r)[13]),"r"((r)[14]),"r"((r)[15]), \
           "r"((r)[16]),"r"((r)[17]),"r"((r)[18]),"r"((r)[19]),"r"((r)[20]),"r"((r)[21]),"r"((r)[22]),"r"((r)[23]), \
           "r"((r)[24]),"r"((r)[25]),"r"((r)[26]),"r"((r)[27]),"r"((r)[28]),"r"((r)[29]),"r"((r)[30]),"r"((r)[31]) \
        : "memory")
#define IDESC_TF32 0x8400910u
__device__ __forceinline__ void mma_ss(uint32_t d, uint64_t a, uint64_t b, bool en) {
    uint32_t e = en ? 1u : 0u;
    asm volatile("{\n\t.reg .pred p;\n\tsetp.ne.u32 p, %5, 0;\n\t"
        "tcgen05.mma.cta_group::1.kind::tf32 [%0], %1, %2, %3, {%4,%4,%4,%4}, p;\n\t}"
        :: "r"(d), "l"(a), "l"(b), "r"(IDESC_TF32), "r"(0u), "r"(e) : "memory");
}
__device__ __forceinline__ void mma_ts(uint32_t d, uint32_t a, uint64_t b, bool en) {
    uint32_t e = en ? 1u : 0u;
    asm volatile("{\n\t.reg .pred p;\n\tsetp.ne.u32 p, %5, 0;\n\t"
        "tcgen05.mma.cta_group::1.kind::tf32 [%0], [%1], %2, %3, {%4,%4,%4,%4}, p;\n\t}"
        :: "r"(d), "r"(a), "l"(b), "r"(IDESC_TF32), "r"(0u), "r"(e) : "memory");
}
__device__ __forceinline__ uint64_t mk_desc(const void* p) {
    return 0x4000404000010000ULL | (ull)((smu32(p) >> 4) & 0x3FFF);
}
#endif

// ---------- generic fp32 GEMM (FFMA2) ----------
#define GBM 64
#define GBN 64
#define GBK 16
__global__ void __launch_bounds__(256) gemm_kernel(
    const float* __restrict__ A0, int K0, const float* __restrict__ A1, int K1,
    const float* __restrict__ W, int ldw, const float* __restrict__ bias,
    float* __restrict__ C, int ldc, int M, int N, int mode)
{
    __shared__ float As[GBK][GBM + 2];
    __shared__ float Wsm[GBK][GBN];
    const int tid = threadIdx.x, tx = tid & 15, ty = tid >> 4;
    const int row0 = blockIdx.x * GBM, col0 = blockIdx.y * GBN;
    const int K = K0 + K1;
    ull acc2[2][4] = {};
    for (int kt = 0; kt < K; kt += GBK) {
        {
            const int m = tid >> 2, kb = (tid & 3) * 4, gr = row0 + m;
            #pragma unroll
            for (int i = 0; i < 4; i++) {
                const int gk = kt + kb + i;
                float v = 0.0f;
                if (gk < K) v = (gk < K0) ? A0[(size_t)gr * K0 + gk] : A1[(size_t)gr * K1 + (gk - K0)];
                As[kb + i][m] = v;
            }
        }
        #pragma unroll
        for (int i = 0; i < 4; i++) {
            const int idx = tid + 256 * i, k = idx >> 6, n = idx & 63;
            const int gk = kt + k, gn = col0 + n;
            Wsm[k][n] = (gk < K && gn < N) ? W[(size_t)gk * ldw + gn] : 0.0f;
        }
        __syncthreads();
        #pragma unroll
        for (int k = 0; k < GBK; k++) {
            const ull a0 = *(const ull*)&As[k][ty * 4];
            const ull a1 = *(const ull*)&As[k][ty * 4 + 2];
            const float4 w4 = *(const float4*)&Wsm[k][tx * 4];
            ull wd[4] = {pack_dup(w4.x), pack_dup(w4.y), pack_dup(w4.z), pack_dup(w4.w)};
            #pragma unroll
            for (int j = 0; j < 4; j++) { fma2(acc2[0][j], a0, wd[j]); fma2(acc2[1][j], a1, wd[j]); }
        }
        __syncthreads();
    }
    #pragma unroll
    for (int i2 = 0; i2 < 2; i2++)
        #pragma unroll
        for (int j = 0; j < 4; j++) {
            float lo, hi; unpack2(acc2[i2][j], lo, hi);
            const int c = col0 + tx * 4 + j;
            if (c >= N) continue;
            float pair[2] = {lo, hi};
            #pragma unroll
            for (int u = 0; u < 2; u++) {
                const int r = row0 + ty * 4 + 2 * i2 + u;
                if (r >= M) continue;
                float v = pair[u];
                if (bias) v += bias[c];
                if (mode == 1) v = silu_f(v);
                else if (mode == 2) v = C[(size_t)r * ldc + c] + silu_f(v);
                C[(size_t)r * ldc + c] = v;
            }
        }
}

__global__ void timefeat_kernel(const float* __restrict__ t, float* __restrict__ feat)
{
    const int idx = blockIdx.x * blockDim.x + threadIdx.x;
    if (idx >= NODES * 128) return;
    const int node = idx >> 7, c = idx & 127, b = node >> 5;
    const float tv = t[b];
    const float kf = -logf(10000.0f) / 63.0f;
    float val = (c < 64) ? sinf(tv * __expf((float)c * kf)) : cosf(tv * __expf((float)(c - 64) * kf));
    feat[(size_t)node * 384 + 256 + c] = val;
}

__global__ void edgefeat_kernel(const float* __restrict__ frac, float* __restrict__ efT)
{
    const int idx = blockIdx.x * blockDim.x + threadIdx.x;
    if (idx >= NEBLK * 128 * 64) return;
    const int bl = idx >> 13, rem = idx & 8191, r = rem >> 6, k = rem & 63;
    const int node = (bl << 2) + (r >> 5), j = r & 31, b = node >> 5;
    float val = 0.0f;
    if (k < 54) {
        const int a = (k < 27) ? k : (k - 27);
        const int dim = a / 9, f = a - dim * 9 + 1;
        float d = frac[(b * 32 + j) * 3 + dim] - frac[node * 3 + dim];
        d -= floorf(d);
        const float arg = d * (6.283185307179586f * (float)f);
        val = (k < 27) ? sinf(arg) : cosf(arg);
    }
    const uint32_t off = (uint32_t)((r >> 3) + (k >> 5) * 16) * 1024u + (r & 7) * 128u + (k & 31) * 4u;
    ((uint32_t*)efT)[(size_t)bl * 8192 + (sw128(off) >> 2)] = tf32b(val);
}

__global__ void pack_w1t_kernel(const float* __restrict__ m1W, float* __restrict__ W1T)
{
    const int idx = blockIdx.x * blockDim.x + threadIdx.x;
    if (idx >= NLAY * 256 * 64) return;
    const int l = idx >> 14, rem = idx & 16383, n = rem >> 6, k = rem & 63;
    float v = 0.0f;
    if (k < 54) {
        const int a = (k < 27) ? k : (k - 27);
        const int dim = a / 9, f = a - dim * 9 + 1;
        const int row = 512 + ((k < 27) ? 0 : 30) + dim * 10 + f;
        v = m1W[(size_t)l * 578 * 256 + row * 256 + n];
    }
    const uint32_t off = (uint32_t)((n >> 3) + (k >> 5) * 32) * 1024u + (n & 7) * 128u + (k & 31) * 4u;
    ((uint32_t*)W1T)[(size_t)l * 16384 + (sw128(off) >> 2)] = tf32b(v);
}

__global__ void pack_w2t_kernel(const float* __restrict__ m2W, float* __restrict__ W2T)
{
    const int idx = blockIdx.x * blockDim.x + threadIdx.x;
    if (idx >= NLAY * 4 * 256 * 64) return;
    const int l = idx >> 16, rem = idx & 65535, q = rem >> 14, r2 = rem & 16383;
    const int n = r2 >> 6, kk = r2 & 63;
    const float v = m2W[(size_t)l * 65536 + (q * 64 + kk) * 256 + n];
    const uint32_t off = (uint32_t)((n >> 3) + (kk >> 5) * 32) * 1024u + (n & 7) * 128u + (kk & 31) * 4u;
    ((uint32_t*)W2T)[((size_t)l * 4 + q) * 16384 + (sw128(off) >> 2)] = tf32b(v);
}

__global__ void prep_kernel(const float* __restrict__ P, const float* __restrict__ W1,
                            const float* __restrict__ lpolar,
                            float* __restrict__ PiQ, float* __restrict__ PjT)
{
    const int node = blockIdx.x, c = threadIdx.x;
    const int gb = node >> 5, j = node & 31;
    float q = W1[542 * 256 + c] + W1[552 * 256 + c] + W1[562 * 256 + c];
    #pragma unroll
    for (int u = 0; u < 6; u++) q += lpolar[gb * 6 + u] * W1[(572 + u) * 256 + c];
    PiQ[(size_t)node * 256 + c] = P[(size_t)node * 512 + c] + q;
    PjT[((size_t)gb * 256 + c) * 32 + j] = P[(size_t)node * 512 + 256 + c];
}

__global__ void layernorm_kernel(const float* __restrict__ x, const float* __restrict__ g,
                                 const float* __restrict__ b, float* __restrict__ y)
{
    const int row = blockIdx.x, tid = threadIdx.x;
    const float v = x[(size_t)row * HID + tid];
    __shared__ float sr[8];
    float s = v;
    #pragma unroll
    for (int o = 16; o; o >>= 1) s += __shfl_xor_sync(~0u, s, o);
    if ((tid & 31) == 0) sr[tid >> 5] = s;
    __syncthreads();
    float tot = 0.0f;
    #pragma unroll
    for (int i = 0; i < 8; i++) tot += sr[i];
    const float mean = tot * (1.0f / 256.0f);
    const float d = v - mean;
    __syncthreads();
    float q = d * d;
    #pragma unroll
    for (int o = 16; o; o >>= 1) q += __shfl_xor_sync(~0u, q, o);
    if ((tid & 31) == 0) sr[tid >> 5] = q;
    __syncthreads();
    tot = 0.0f;
    #pragma unroll
    for (int i = 0; i < 8; i++) tot += sr[i];
    y[(size_t)row * HID + tid] = d * rsqrtf(tot * (1.0f / 256.0f) + 1e-5f) * g[tid] + b[tid];
}

// ---------- fused edge kernel: tensor path (sm_103a) / scalar fallback ----------
#define EDGE_SMEM_REQ (224 * 1024 + 1024)
__global__ void __launch_bounds__(256, 1) edge_msg_tc(
    const float* __restrict__ PiQ, const float* __restrict__ PjT,
    const float* __restrict__ efT, const float* __restrict__ W1T,
    const float* __restrict__ W2T, const float* __restrict__ b2,
    float* __restrict__ msg)
{
    extern __shared__ char smraw[];
#if HAS_TC
    char* sb = (char*)(((uintptr_t)smraw + 1023) & ~(uintptr_t)1023);
    float* efs  = (float*)sb;
    float* W1s  = (float*)(sb + 32768);
    float* buf0 = (float*)(sb + 98304);
    float* buf1 = (float*)(sb + 163840);
    __shared__ uint32_t s_tmem[1];
    __shared__ __align__(8) unsigned long long s_bar[3];

    const int tid = threadIdx.x, wid = tid >> 5, lid = tid & 31;
    const int bl = blockIdx.x, node0 = bl << 2, gb = node0 >> 5;
    const uint32_t barE = smu32(&s_bar[0]), barA = smu32(&s_bar[1]), barB = smu32(&s_bar[2]);

    if (tid == 0) { mbar_init(barE, 1); mbar_init(barA, 1); mbar_init(barB, 1); }
    if (wid == 0)
        asm volatile("tcgen05.alloc.cta_group::1.sync.aligned.shared::cta.b32 [%0], 512;"
                     :: "r"(smu32(s_tmem)) : "memory");
    __syncthreads();
    const uint32_t tb = s_tmem[0];

    {
        const float4* g = (const float4*)(efT + (size_t)bl * 8192);
        for (int i = tid; i < 2048; i += 256) cp16(((float4*)efs) + i, g + i);
        const float4* gw = (const float4*)W1T;
        for (int i = tid; i < 4096; i += 256) cp16(((float4*)W1s) + i, gw + i);
    }
    cp_commit();
    { const float4* g = (const float4*)W2T;
      for (int i = tid; i < 4096; i += 256) cp16(((float4*)buf0) + i, g + i); }
    cp_commit();
    { const float4* g = (const float4*)(W2T + 16384);
      for (int i = tid; i < 4096; i += 256) cp16(((float4*)buf1) + i, g + i); }
    cp_commit();

    cp_wait<2>();
    fence_pa();
    __syncthreads();

    if (tid == 0) {
        const uint64_t ad = mk_desc(efs), bd = mk_desc(W1s);
        #pragma unroll
        for (int s = 0; s < 8; s++)
            mma_ss(tb, ad + (uint64_t)((s >> 2) * 1024 + (s & 3) * 2),
                       bd + (uint64_t)((s >> 2) * 2048 + (s & 3) * 2), s > 0);
        tc_commit(barE);
    }
    mbar_wait(barE, 0);
    tcf_a();

    const int nodeL = wid & 3, chalf = (wid >> 2) * 128;
    const int node = node0 + nodeL;
    const float* piqp = PiQ + (size_t)node * 256;
    #pragma unroll 1
    for (int i = 0; i < 4; i++) {
        const int c0 = chalf + 32 * i;
        uint32_t r[32];
        TC_LD_X32(r, tb + c0);
        tcw_ld();
        float piq[32];
        #pragma unroll
        for (int u = 0; u < 8; u++) *(float4*)&piq[4 * u] = ((const float4*)(piqp + c0))[u];
        #pragma unroll
        for (int c = 0; c < 32; c++) {
            const float pj = PjT[((size_t)(gb * 256 + c0 + c)) * 32 + lid];
            r[c] = tf32b(silu_f(__uint_as_float(r[c]) + piq[c] + pj));
        }
        TC_ST_X32(tb + 256 + c0 + ((uint32_t)nodeL << 21), r);
    }
    tcw_st();
    tcf_b();
    __syncthreads();

    cp_wait<1>();
    fence_pa();
    __syncthreads();
    if (tid == 0) {
        tcf_a();
        const uint64_t bd = mk_desc(buf0);
        #pragma unroll
        for (int s = 0; s < 8; s++)
            mma_ts(tb, tb + 256 + 8 * s, bd + (uint64_t)((s >> 2) * 2048 + (s & 3) * 2), s > 0);
        tc_commit(barA);
    }
    cp_wait<0>();
    fence_pa();
    __syncthreads();
    if (tid == 0) {
        const uint64_t bd = mk_desc(buf1);
        #pragma unroll
        for (int s = 0; s < 8; s++)
            mma_ts(tb, tb + 256 + 64 + 8 * s, bd + (uint64_t)((s >> 2) * 2048 + (s & 3) * 2), true);
        tc_commit(barB);
    }
    mbar_wait(barA, 0);
    { const float4* g = (const float4*)(W2T + 2 * 16384);
      for (int i = tid; i < 4096; i += 256) cp16(((float4*)buf0) + i, g + i); }
    cp_commit();
    cp_wait<0>();
    fence_pa();
    __syncthreads();
    if (tid == 0) {
        const uint64_t bd = mk_desc(buf0);
        #pragma unroll
        for (int s = 0; s < 8; s++)
            mma_ts(tb, tb + 256 + 128 + 8 * s, bd + (uint64_t)((s >> 2) * 2048 + (s & 3) * 2), true);
        tc_commit(barA);
    }
    mbar_wait(barB, 0);
    { const float4* g = (const float4*)(W2T + 3 * 16384);
      for (int i = tid; i < 4096; i += 256) cp16(((float4*)buf1) + i, g + i); }
    cp_commit();
    cp_wait<0>();
    fence_pa();
    __syncthreads();
    if (tid == 0) {
        const uint64_t bd = mk_desc(buf1);
        #pragma unroll
        for (int s = 0; s < 8; s++)
            mma_ts(tb, tb + 256 + 192 + 8 * s, bd + (uint64_t)((s >> 2) * 2048 + (s & 3) * 2), true);
        tc_commit(barB);
    }

    mbar_wait(barA, 1);
    mbar_wait(barB, 1);
    tcf_a();

    #pragma unroll 1
    for (int i = 0; i < 4; i++) {
        const int c0 = chalf + 32 * i;
        uint32_t r[32];
        TC_LD_X32(r, tb + c0);
        tcw_ld();
        float bb[32];
        #pragma unroll
        for (int u = 0; u < 8; u++) *(float4*)&bb[4 * u] = ((const float4*)(b2 + c0))[u];
        float y[32];
        #pragma unroll
        for (int c = 0; c < 32; c++) y[c] = silu_f(__uint_as_float(r[c]) + bb[c]);
        #pragma unroll
        for (int o = 16; o; o >>= 1)
            #pragma unroll
            for (int c = 0; c < 32; c++) y[c] += __shfl_xor_sync(~0u, y[c], o);
        msg[(size_t)node * 256 + c0 + lid] = y[lid] * (1.0f / 32.0f);
    }

    __syncthreads();
    if (wid == 0) {
        asm volatile("tcgen05.relinquish_alloc_permit.cta_group::1.sync.aligned;");
        asm volatile("tcgen05.dealloc.cta_group::1.sync.aligned.b32 %0, 512;" :: "r"(tb));
    }
#else
    // scalar fallback (correct; runs only if the 'a'-target cubin is absent)
    float* Xf = (float*)smraw;   // [32][260]
    const int tid = threadIdx.x, bl = blockIdx.x, node0 = bl << 2, gb = node0 >> 5;
    const uint32_t* efb = (const uint32_t*)efT + (size_t)bl * 8192;
    const uint32_t* w1b = (const uint32_t*)W1T;
    const uint32_t* w2b = (const uint32_t*)W2T;
    for (int nl = 0; nl < 4; nl++) {
        const int node = node0 + nl;
        for (int idx = tid; idx < 32 * 256; idx += 256) {
            const int j = idx >> 8, c = idx & 255;
            const int r = nl * 32 + j;
            float e = 0.f;
            for (int k = 0; k < 54; k++) {
                uint32_t oa = (uint32_t)((r >> 3) + (k >> 5) * 16) * 1024u + (r & 7) * 128u + (k & 31) * 4u;
                uint32_t ob = (uint32_t)((c >> 3) + (k >> 5) * 32) * 1024u + (c & 7) * 128u + (k & 31) * 4u;
                e += __uint_as_float(efb[sw128(oa) >> 2]) * __uint_as_float(w1b[sw128(ob) >> 2]);
            }
            e += PiQ[(size_t)node * 256 + c] + PjT[((size_t)(gb * 256 + c)) * 32 + j];
            Xf[j * 260 + c] = silu_f(e);
        }
        __syncthreads();
        const int c = tid;
        float acc = 0.f;
        for (int j = 0; j < 32; j++) {
            float y = b2[c];
            for (int k = 0; k < 256; k++) {
                uint32_t ob = (uint32_t)((c >> 3) + ((k & 63) >> 5) * 32) * 1024u + (c & 7) * 128u + (k & 31) * 4u;
                y += Xf[j * 260 + k] * __uint_as_float(w2b[(k >> 6) * 16384 + (sw128(ob) >> 2)]);
            }
            acc += silu_f(y);
        }
        msg[(size_t)node * 256 + c] = acc * (1.0f / 32.0f);
        __syncthreads();
    }
#endif
}

__global__ void graphmean_kernel(const float* __restrict__ h, float* __restrict__ gf)
{
    const int b = blockIdx.x, c = threadIdx.x;
    float s = 0.0f;
    #pragma unroll
    for (int i = 0; i < 32; i++) s += h[(size_t)((b << 5) + i) * HID + c];
    gf[(size_t)b * HID + c] = s * (1.0f / 32.0f);
}

static void run_gemm(cudaStream_t s, const float* A0, int K0, const float* A1, int K1,
                     const float* W, int ldw, const float* bias,
                     float* C, int ldc, int M, int N, int mode)
{
    dim3 grid((M + GBM - 1) / GBM, (N + GBN - 1) / GBN);
    gemm_kernel<<<grid, 256, 0, s>>>(A0, K0, A1, K1, W, ldw, bias, C, ldc, M, N, mode);
}

extern "C" void kernel_launch(void* const* d_in, const int* in_sizes, int n_in,
                              void* d_out, int out_size)
{
    const float* t          = (const float*)d_in[0];
    const float* atom_types = (const float*)d_in[1];
    const float* frac       = (const float*)d_in[2];
    const float* l_polar    = (const float*)d_in[3];
    const float* Ws      = (const float*)d_in[5];
    const float* bs      = (const float*)d_in[6];
    const float* Wn      = (const float*)d_in[7];
    const float* bn      = (const float*)d_in[8];
    const float* ln_g    = (const float*)d_in[9];
    const float* ln_b    = (const float*)d_in[10];
    const float* m1_W    = (const float*)d_in[11];
    const float* m1_b    = (const float*)d_in[12];
    const float* m2_W    = (const float*)d_in[13];
    const float* m2_b    = (const float*)d_in[14];
    const float* a1_W    = (const float*)d_in[15];
    const float* a1_b    = (const float*)d_in[16];
    const float* a2_W    = (const float*)d_in[17];
    const float* a2_b    = (const float*)d_in[18];
    const float* fln_g   = (const float*)d_in[19];
    const float* fln_b   = (const float*)d_in[20];
    const float* type_W  = (const float*)d_in[21];
    const float* type_b  = (const float*)d_in[22];
    const float* polar_W = (const float*)d_in[23];
    const float* frac_W  = (const float*)d_in[24];
    float* out = (float*)d_out;

    float *feat, *nf, *h, *P, *PiQ, *PjT, *msg, *act, *gf, *efT, *W1T, *W2T;
    cudaGetSymbolAddress((void**)&feat, g_feat);
    cudaGetSymbolAddress((void**)&nf,   g_nf);
    cudaGetSymbolAddress((void**)&h,    g_h);
    cudaGetSymbolAddress((void**)&P,    g_P);
    cudaGetSymbolAddress((void**)&PiQ,  g_PiQ);
    cudaGetSymbolAddress((void**)&PjT,  g_PjT);
    cudaGetSymbolAddress((void**)&msg,  g_msg);
    cudaGetSymbolAddress((void**)&act,  g_act);
    cudaGetSymbolAddress((void**)&gf,   g_gf);
    cudaGetSymbolAddress((void**)&efT,  g_efT);
    cudaGetSymbolAddress((void**)&W1T,  g_W1T);
    cudaGetSymbolAddress((void**)&W2T,  g_W2T);

    cudaFuncSetAttribute(edge_msg_tc, cudaFuncAttributeMaxDynamicSharedMemorySize, EDGE_SMEM_REQ);
    cudaStream_t s = 0;

    timefeat_kernel<<<(NODES * 128 + 255) / 256, 256, 0, s>>>(t, feat);
    run_gemm(s, atom_types, TYPED, nullptr, 0, Ws, HID, bs, feat, 384, NODES, HID, 0);
    run_gemm(s, feat, 384, nullptr, 0, Wn, HID, bn, nf, HID, NODES, HID, 0);

    edgefeat_kernel<<<(NEBLK * 128 * 64) / 256, 256, 0, s>>>(frac, efT);
    pack_w1t_kernel<<<(NLAY * 256 * 64) / 256, 256, 0, s>>>(m1_W, W1T);
    pack_w2t_kernel<<<(NLAY * 4 * 256 * 64) / 256, 256, 0, s>>>(m2_W, W2T);

    for (int l = 0; l < NLAY; l++) {
        const float* W1 = m1_W + (size_t)l * 578 * HID;
        layernorm_kernel<<<NODES, 256, 0, s>>>(nf, ln_g + l * HID, ln_b + l * HID, h);
        run_gemm(s, h, HID, nullptr, 0, W1, HID, m1_b + l * HID, P, 512, NODES, HID, 0);
        run_gemm(s, h, HID, nullptr, 0, W1 + 256 * HID, HID, nullptr, P + 256, 512, NODES, HID, 0);
        prep_kernel<<<NODES, 256, 0, s>>>(P, W1, l_polar, PiQ, PjT);
        edge_msg_tc<<<NEBLK, 256, EDGE_SMEM_REQ, s>>>(
            PiQ, PjT, efT, W1T + (size_t)l * 16384, W2T + (size_t)l * 65536,
            m2_b + l * HID, msg);
        run_gemm(s, nf, HID, msg, HID, a1_W + (size_t)l * 512 * HID, HID,
                 a1_b + l * HID, act, HID, NODES, HID, 1);
        run_gemm(s, act, HID, nullptr, 0, a2_W + (size_t)l * HID * HID, HID,
                 a2_b + l * HID, nf, HID, NODES, HID, 2);
    }

    layernorm_kernel<<<NODES, 256, 0, s>>>(nf, fln_g, fln_b, h);
    graphmean_kernel<<<BGR, 256, 0, s>>>(h, gf);

    run_gemm(s, h, HID, nullptr, 0, type_W, TYPED, type_b, out, TYPED, NODES, TYPED, 0);
    run_gemm(s, gf, HID, nullptr, 0, polar_W, 6, nullptr, out + (size_t)NODES * TYPED, 6, BGR, 6, 0);
    run_gemm(s, h, HID, nullptr, 0, frac_W, 3, nullptr,
             out + (size_t)NODES * TYPED + (size_t)BGR * 6, 3, NODES, 3, 0);
}

// round 6
// speedup vs baseline: 2.9482x; 2.3624x over previous
#include <cuda_runtime.h>
#include <cuda_bf16.h>
#include <math.h>
#include <stdint.h>

#define BGR   128
#define NODES 4096
#define HID   256
#define TYPED 100
#define NLAY  4
#define NTILE 1024          // 128 graphs x 8 tiles; tile = 4 nodes = 128 edge rows

#if defined(__CUDA_ARCH_FEAT_SM103_ALL) || defined(__CUDA_ARCH_FEAT_SM100_ALL) || defined(__CUDA_ARCH_SPECIFIC__) || defined(__CUDA_ARCH_FAMILY_SPECIFIC__)
#define HAS_TC 1
#else
#define HAS_TC 0
#endif

__device__ float g_feat[NODES * 384];
__device__ float g_nf  [NODES * HID];
__device__ float g_h   [NODES * HID];
__device__ float g_P   [NODES * 512];
__device__ float g_PiQ [NODES * HID];
__device__ float g_PjT [BGR * HID * 32];
__device__ float g_msg [NODES * HID];
__device__ float g_act [NODES * HID];
__device__ float g_gf  [BGR * HID];
__device__ __nv_bfloat16 g_efT [(size_t)NTILE * 128 * 64];   // swizzled 16KB tiles
__device__ __nv_bfloat16 g_W1T [NLAY * 256 * 64];            // swizzled [n][k]
__device__ __nv_bfloat16 g_W2T [NLAY * 256 * 256];           // blocked-atom swizzled [n][k]

typedef unsigned long long ull;

__device__ __forceinline__ float silu_f(float x) { return x / (1.0f + __expf(-x)); }
__device__ __forceinline__ float silu_t(float x) {
    float xh = 0.5f * x, t;
    asm("tanh.approx.f32 %0, %1;" : "=f"(t) : "f"(xh));
    return fmaf(xh, t, xh);
}
__device__ __forceinline__ ull pack_dup(float f) { ull r; asm("mov.b64 %0, {%1,%1};" : "=l"(r) : "f"(f)); return r; }
__device__ __forceinline__ void unpack2(ull v, float& lo, float& hi) { asm("mov.b64 {%0,%1}, %2;" : "=f"(lo), "=f"(hi) : "l"(v)); }
__device__ __forceinline__ void fma2(ull& a, ull x, ull y) { asm("fma.rn.f32x2 %0, %1, %2, %0;" : "+l"(a) : "l"(x), "l"(y)); }
__device__ __forceinline__ void cp16(void* sdst, const void* gsrc) {
    unsigned s = (unsigned)__cvta_generic_to_shared(sdst);
    asm volatile("cp.async.cg.shared.global [%0], [%1], 16;" :: "r"(s), "l"(gsrc));
}
__device__ __forceinline__ void cp_commit() { asm volatile("cp.async.commit_group;"); }
template<int N> __device__ __forceinline__ void cp_wait() { asm volatile("cp.async.wait_group %0;" :: "n"(N)); }
__device__ __forceinline__ uint32_t smu32(const void* p) { return (uint32_t)__cvta_generic_to_shared(p); }
__device__ __forceinline__ void mbar_init(uint32_t a, uint32_t c) {
    asm volatile("mbarrier.init.shared.b64 [%0], %1;" :: "r"(a), "r"(c) : "memory");
}
__device__ __forceinline__ void mbar_wait(uint32_t a, uint32_t ph) {
    asm volatile("{\n\t.reg .pred P;\nWL%=:\n\t"
        "mbarrier.try_wait.parity.acquire.cta.shared::cta.b64 P, [%0], %1, 0x989680;\n\t"
        "@!P bra WL%=;\n\t}" :: "r"(a), "r"(ph) : "memory");
}
__device__ __forceinline__ void fence_pa() { asm volatile("fence.proxy.async.shared::cta;" ::: "memory"); }
__device__ __forceinline__ uint32_t sw128(uint32_t b) { return b ^ ((b >> 3) & 0x70); }

#if HAS_TC
__device__ __forceinline__ void tcf_b() { asm volatile("tcgen05.fence::before_thread_sync;" ::: "memory"); }
__device__ __forceinline__ void tcf_a() { asm volatile("tcgen05.fence::after_thread_sync;" ::: "memory"); }
__device__ __forceinline__ void tcw_ld() { asm volatile("tcgen05.wait::ld.sync.aligned;" ::: "memory"); }
__device__ __forceinline__ void tcw_st() { asm volatile("tcgen05.wait::st.sync.aligned;" ::: "memory"); }
__device__ __forceinline__ void tc_commit(uint32_t b) {
    asm volatile("tcgen05.commit.cta_group::1.mbarrier::arrive::one.shared::cluster.b64 [%0];" :: "r"(b) : "memory");
}
#define TC_LD_X32(r, a) \
    asm volatile("tcgen05.ld.sync.aligned.32x32b.x32.b32 " \
        "{%0,%1,%2,%3,%4,%5,%6,%7,%8,%9,%10,%11,%12,%13,%14,%15," \
        "%16,%17,%18,%19,%20,%21,%22,%23,%24,%25,%26,%27,%28,%29,%30,%31}, [%32];" \
        : "=r"((r)[0]),"=r"((r)[1]),"=r"((r)[2]),"=r"((r)[3]),"=r"((r)[4]),"=r"((r)[5]),"=r"((r)[6]),"=r"((r)[7]), \
          "=r"((r)[8]),"=r"((r)[9]),"=r"((r)[10]),"=r"((r)[11]),"=r"((r)[12]),"=r"((r)[13]),"=r"((r)[14]),"=r"((r)[15]), \
          "=r"((r)[16]),"=r"((r)[17]),"=r"((r)[18]),"=r"((r)[19]),"=r"((r)[20]),"=r"((r)[21]),"=r"((r)[22]),"=r"((r)[23]), \
          "=r"((r)[24]),"=r"((r)[25]),"=r"((r)[26]),"=r"((r)[27]),"=r"((r)[28]),"=r"((r)[29]),"=r"((r)[30]),"=r"((r)[31]) \
        : "r"(a))
#define TC_ST_X16(a, r) \
    asm volatile("tcgen05.st.sync.aligned.32x32b.x16.b32 [%0], " \
        "{%1,%2,%3,%4,%5,%6,%7,%8,%9,%10,%11,%12,%13,%14,%15,%16};" \
        :: "r"(a), \
           "r"((r)[0]),"r"((r)[1]),"r"((r)[2]),"r"((r)[3]),"r"((r)[4]),"r"((r)[5]),"r"((r)[6]),"r"((r)[7]), \
           "r"((r)[8]),"r"((r)[9]),"r"((r)[10]),"r"((r)[11]),"r"((r)[12]),"r"((r)[13]),"r"((r)[14]),"r"((r)[15]) \
        : "memory")
// idesc kind::f16: dtype F32 | atype BF16 | btype BF16 | N=256 | M=128
#define IDESC_BF16 0x8400490u
__device__ __forceinline__ void mma_f16_ss(uint32_t d, uint64_t a, uint64_t b, bool en) {
    uint32_t e = en ? 1u : 0u;
    asm volatile("{\n\t.reg .pred p;\n\tsetp.ne.u32 p, %5, 0;\n\t"
        "tcgen05.mma.cta_group::1.kind::f16 [%0], %1, %2, %3, {%4,%4,%4,%4}, p;\n\t}"
        :: "r"(d), "l"(a), "l"(b), "r"(IDESC_BF16), "r"(0u), "r"(e) : "memory");
}
__device__ __forceinline__ void mma_f16_ts(uint32_t d, uint32_t a, uint64_t b, bool en) {
    uint32_t e = en ? 1u : 0u;
    asm volatile("{\n\t.reg .pred p;\n\tsetp.ne.u32 p, %5, 0;\n\t"
        "tcgen05.mma.cta_group::1.kind::f16 [%0], [%1], %2, %3, {%4,%4,%4,%4}, p;\n\t}"
        :: "r"(d), "r"(a), "l"(b), "r"(IDESC_BF16), "r"(0u), "r"(e) : "memory");
}
__device__ __forceinline__ uint64_t mk_desc(const void* p) {
    return 0x4000404000010000ULL | (ull)((smu32(p) >> 4) & 0x3FFF);
}
#endif

// ---------- generic fp32 GEMM (FFMA2) ----------
#define GBM 64
#define GBN 64
#define GBK 16
__global__ void __launch_bounds__(256) gemm_kernel(
    const float* __restrict__ A0, int K0, const float* __restrict__ A1, int K1,
    const float* __restrict__ W, int ldw, const float* __restrict__ bias,
    float* __restrict__ C, int ldc, int M, int N, int mode)
{
    __shared__ float As[GBK][GBM + 2];
    __shared__ float Wsm[GBK][GBN];
    const int tid = threadIdx.x, tx = tid & 15, ty = tid >> 4;
    const int row0 = blockIdx.x * GBM, col0 = blockIdx.y * GBN;
    const int K = K0 + K1;
    ull acc2[2][4] = {};
    for (int kt = 0; kt < K; kt += GBK) {
        {
            const int m = tid >> 2, kb = (tid & 3) * 4, gr = row0 + m;
            #pragma unroll
            for (int i = 0; i < 4; i++) {
                const int gk = kt + kb + i;
                float v = 0.0f;
                if (gk < K) v = (gk < K0) ? A0[(size_t)gr * K0 + gk] : A1[(size_t)gr * K1 + (gk - K0)];
                As[kb + i][m] = v;
            }
        }
        #pragma unroll
        for (int i = 0; i < 4; i++) {
            const int idx = tid + 256 * i, k = idx >> 6, n = idx & 63;
            const int gk = kt + k, gn = col0 + n;
            Wsm[k][n] = (gk < K && gn < N) ? W[(size_t)gk * ldw + gn] : 0.0f;
        }
        __syncthreads();
        #pragma unroll
        for (int k = 0; k < GBK; k++) {
            const ull a0 = *(const ull*)&As[k][ty * 4];
            const ull a1 = *(const ull*)&As[k][ty * 4 + 2];
            const float4 w4 = *(const float4*)&Wsm[k][tx * 4];
            ull wd[4] = {pack_dup(w4.x), pack_dup(w4.y), pack_dup(w4.z), pack_dup(w4.w)};
            #pragma unroll
            for (int j = 0; j < 4; j++) { fma2(acc2[0][j], a0, wd[j]); fma2(acc2[1][j], a1, wd[j]); }
        }
        __syncthreads();
    }
    #pragma unroll
    for (int i2 = 0; i2 < 2; i2++)
        #pragma unroll
        for (int j = 0; j < 4; j++) {
            float lo, hi; unpack2(acc2[i2][j], lo, hi);
            const int c = col0 + tx * 4 + j;
            if (c >= N) continue;
            float pair[2] = {lo, hi};
            #pragma unroll
            for (int u = 0; u < 2; u++) {
                const int r = row0 + ty * 4 + 2 * i2 + u;
                if (r >= M) continue;
                float v = pair[u];
                if (bias) v += bias[c];
                if (mode == 1) v = silu_f(v);
                else if (mode == 2) v = C[(size_t)r * ldc + c] + silu_f(v);
                C[(size_t)r * ldc + c] = v;
            }
        }
}

__global__ void timefeat_kernel(const float* __restrict__ t, float* __restrict__ feat)
{
    const int idx = blockIdx.x * blockDim.x + threadIdx.x;
    if (idx >= NODES * 128) return;
    const int node = idx >> 7, c = idx & 127, b = node >> 5;
    const float tv = t[b];
    const float kf = -logf(10000.0f) / 63.0f;
    float val = (c < 64) ? sinf(tv * __expf((float)c * kf)) : cosf(tv * __expf((float)(c - 64) * kf));
    feat[(size_t)node * 384 + 256 + c] = val;
}

// efT tile (tI = node0/4): (r,k) -> byte tI*16384 + sw128(r*128 + k*2); k<27 sin, 27..53 cos
__global__ void edgefeat_kernel(const float* __restrict__ frac, __nv_bfloat16* __restrict__ efT)
{
    const int idx = blockIdx.x * blockDim.x + threadIdx.x;
    if (idx >= NTILE * 128 * 64) return;
    const int tI = idx >> 13, rem = idx & 8191, r = rem >> 6, k = rem & 63;
    const int node = (tI << 2) + (r >> 5), j = r & 31, b = node >> 5;
    float val = 0.0f;
    if (k < 54) {
        const int a = (k < 27) ? k : (k - 27);
        const int dim = a / 9, f = a - dim * 9 + 1;
        float d = frac[(b * 32 + j) * 3 + dim] - frac[node * 3 + dim];
        d -= floorf(d);
        const float arg = d * (6.283185307179586f * (float)f);
        val = (k < 27) ? sinf(arg) : cosf(arg);
    }
    *(__nv_bfloat16*)((char*)efT + (size_t)tI * 16384 + sw128((uint32_t)(r * 128 + k * 2))) =
        __float2bfloat16(val);
}

__global__ void pack_w1t_kernel(const float* __restrict__ m1W, __nv_bfloat16* __restrict__ W1T)
{
    const int idx = blockIdx.x * blockDim.x + threadIdx.x;
    if (idx >= NLAY * 256 * 64) return;
    const int l = idx >> 14, rem = idx & 16383, n = rem >> 6, k = rem & 63;
    float v = 0.0f;
    if (k < 54) {
        const int a = (k < 27) ? k : (k - 27);
        const int dim = a / 9, f = a - dim * 9 + 1;
        const int row = 512 + ((k < 27) ? 0 : 30) + dim * 10 + f;
        v = m1W[(size_t)l * 578 * 256 + row * 256 + n];
    }
    *(__nv_bfloat16*)((char*)W1T + (size_t)l * 32768 + sw128((uint32_t)(n * 128 + k * 2))) =
        __float2bfloat16(v);
}

// W2T blocked atoms: byte = l*131072 + (k>>6)*32768 + (n>>3)*1024 + sw128((n&7)*128 + (k&63)*2)
__global__ void pack_w2t_kernel(const float* __restrict__ m2W, __nv_bfloat16* __restrict__ W2T)
{
    const int idx = blockIdx.x * blockDim.x + threadIdx.x;
    if (idx >= NLAY * 256 * 256) return;
    const int l = idx >> 16, rem = idx & 65535, n = rem >> 8, k = rem & 255;
    const float v = m2W[(size_t)l * 65536 + k * 256 + n];
    const size_t byte = (size_t)l * 131072 + (k >> 6) * 32768 + (n >> 3) * 1024
                      + sw128((uint32_t)((n & 7) * 128 + (k & 63) * 2));
    *(__nv_bfloat16*)((char*)W2T + byte) = __float2bfloat16(v);
}

__global__ void prep_kernel(const float* __restrict__ P, const float* __restrict__ W1,
                            const float* __restrict__ lpolar,
                            float* __restrict__ PiQ, float* __restrict__ PjT)
{
    const int node = blockIdx.x, c = threadIdx.x;
    const int gb = node >> 5, j = node & 31;
    float q = W1[542 * 256 + c] + W1[552 * 256 + c] + W1[562 * 256 + c];
    #pragma unroll
    for (int u = 0; u < 6; u++) q += lpolar[gb * 6 + u] * W1[(572 + u) * 256 + c];
    PiQ[(size_t)node * 256 + c] = P[(size_t)node * 512 + c] + q;
    PjT[((size_t)gb * 256 + c) * 32 + j] = P[(size_t)node * 512 + 256 + c];
}

__global__ void layernorm_kernel(const float* __restrict__ x, const float* __restrict__ g,
                                 const float* __restrict__ b, float* __restrict__ y)
{
    const int row = blockIdx.x, tid = threadIdx.x;
    const float v = x[(size_t)row * HID + tid];
    __shared__ float sr[8];
    float s = v;
    #pragma unroll
    for (int o = 16; o; o >>= 1) s += __shfl_xor_sync(~0u, s, o);
    if ((tid & 31) == 0) sr[tid >> 5] = s;
    __syncthreads();
    float tot = 0.0f;
    #pragma unroll
    for (int i = 0; i < 8; i++) tot += sr[i];
    const float mean = tot * (1.0f / 256.0f);
    const float d = v - mean;
    __syncthreads();
    float q = d * d;
    #pragma unroll
    for (int o = 16; o; o >>= 1) q += __shfl_xor_sync(~0u, q, o);
    if ((tid & 31) == 0) sr[tid >> 5] = q;
    __syncthreads();
    tot = 0.0f;
    #pragma unroll
    for (int i = 0; i < 8; i++) tot += sr[i];
    y[(size_t)row * HID + tid] = d * rsqrtf(tot * (1.0f / 256.0f) + 1e-5f) * g[tid] + b[tid];
}

// ---------- fused edge kernel: 1 block per graph, 8 tiles, bf16 MMA ----------
// smem: efb0 @0 (16K) | efb1 @16K | W1s @32K (32K) | Pjs @64K (32K) | W2s @96K (128K)
#define EDGE_SMEM_REQ 230400
__global__ void __launch_bounds__(256, 1) edge_msg_tc(
    const float* __restrict__ PiQ, const float* __restrict__ PjT,
    const __nv_bfloat16* __restrict__ efT, const __nv_bfloat16* __restrict__ W1T,
    const __nv_bfloat16* __restrict__ W2T, const float* __restrict__ b2,
    float* __restrict__ msg)
{
    extern __shared__ char smraw[];
#if HAS_TC
    char* sb = (char*)(((uintptr_t)smraw + 1023) & ~(uintptr_t)1023);
    float* Pjs = (float*)(sb + 65536);
    __shared__ uint32_t s_tmem[1];
    __shared__ __align__(8) unsigned long long s_bar[2];

    const int tid = threadIdx.x, wid = tid >> 5, lid = tid & 31;
    const int gb = blockIdx.x;
    const uint32_t barE = smu32(&s_bar[0]), barY = smu32(&s_bar[1]);

    if (tid == 0) { mbar_init(barE, 1); mbar_init(barY, 1); }
    if (wid == 0)
        asm volatile("tcgen05.alloc.cta_group::1.sync.aligned.shared::cta.b32 [%0], 512;"
                     :: "r"(smu32(s_tmem)) : "memory");
    __syncthreads();
    const uint32_t tb = s_tmem[0];

    // prologue: g1 = ef tile0 ; g2 = W1+W2+Pjs ; g3 = ef tile1
    {
        const float4* g = (const float4*)efT + (size_t)gb * 8192;
        for (int i = tid; i < 1024; i += 256) cp16((float4*)sb + i, g + i);
    }
    cp_commit();
    {
        const float4* g1 = (const float4*)W1T;
        for (int i = tid; i < 2048; i += 256) cp16((float4*)(sb + 32768) + i, g1 + i);
        const float4* gp = (const float4*)(PjT + (size_t)gb * 8192);
        for (int i = tid; i < 2048; i += 256) cp16((float4*)(sb + 65536) + i, gp + i);
        const float4* g2 = (const float4*)W2T;
        for (int i = tid; i < 8192; i += 256) cp16((float4*)(sb + 98304) + i, g2 + i);
    }
    cp_commit();
    {
        const float4* g = (const float4*)efT + (size_t)gb * 8192 + 1024;
        for (int i = tid; i < 1024; i += 256) cp16((float4*)(sb + 16384) + i, g + i);
    }
    cp_commit();

    const uint64_t w1d = mk_desc(sb + 32768);
    const uint64_t w2d = mk_desc(sb + 98304);
    const int half = wid >> 2, nodeL = wid & 3;

    #pragma unroll 1
    for (int t = 0; t < 8; t++) {
        char* efb = sb + (t & 1) * 16384;
        const int node = gb * 32 + 4 * t + nodeL;
        const uint32_t ph = (uint32_t)(t & 1);

        cp_wait<1>();
        fence_pa();
        __syncthreads();
        // MMA1: E[128,256] = ef @ W1^T  (K=64, 4 steps)
        if (tid == 0) {
            const uint64_t ad = mk_desc(efb);
            #pragma unroll
            for (int s = 0; s < 4; s++) mma_f16_ss(tb, ad + 2 * s, w1d + 2 * s, s > 0);
            tc_commit(barE);
        }
        mbar_wait(barE, ph);
        tcf_a();
        // refill ef[t+2] into this buffer (MMA1 done reading it)
        if (t < 6) {
            const float4* g = (const float4*)efT + (size_t)(gb * 8 + t + 2) * 1024;
            for (int i = tid; i < 1024; i += 256) cp16((float4*)efb + i, g + i);
        }
        cp_commit();

        // phase1: X = silu(E + PiQ + Pj) -> bf16x2 TMEM cols 384..511
        const float* piqp = PiQ + (size_t)node * 256;
        #pragma unroll 1
        for (int i = 0; i < 4; i++) {
            const int c0 = half * 128 + 32 * i;
            uint32_t r[32];
            TC_LD_X32(r, tb + c0);
            tcw_ld();
            float piq[32];
            #pragma unroll
            for (int u = 0; u < 8; u++) *(float4*)&piq[4 * u] = ((const float4*)(piqp + c0))[u];
            float v[32];
            #pragma unroll
            for (int c = 0; c < 32; c++)
                v[c] = silu_t(__uint_as_float(r[c]) + piq[c] + Pjs[(c0 + c) * 32 + lid]);
            uint32_t xp[16];
            #pragma unroll
            for (int p = 0; p < 16; p++)
                asm("cvt.rn.bf16x2.f32 %0, %1, %2;" : "=r"(xp[p]) : "f"(v[2 * p + 1]), "f"(v[2 * p]));
            TC_ST_X16(tb + 384 + half * 64 + 16 * i + ((uint32_t)nodeL << 21), xp);
        }
        tcw_st();
        tcf_b();
        __syncthreads();

        // MMA2: Y = X @ W2^T  (K=256, 16 steps; W2 resident)
        if (tid == 0) {
            tcf_a();
            #pragma unroll
            for (int s = 0; s < 16; s++)
                mma_f16_ts(tb, tb + 384 + 8 * s, w2d + (uint64_t)((s >> 2) * 2048 + (s & 3) * 2), s > 0);
            tc_commit(barY);
        }
        mbar_wait(barY, ph);
        tcf_a();

        // epilogue: silu(Y+b2), mean over 32 lanes via compacting reduce
        #pragma unroll 1
        for (int i = 0; i < 4; i++) {
            const int c0 = half * 128 + 32 * i;
            uint32_t r[32];
            TC_LD_X32(r, tb + c0);
            tcw_ld();
            float bb[32];
            #pragma unroll
            for (int u = 0; u < 8; u++) *(float4*)&bb[4 * u] = ((const float4*)(b2 + c0))[u];
            float v[32];
            #pragma unroll
            for (int c = 0; c < 32; c++) v[c] = silu_t(__uint_as_float(r[c]) + bb[c]);
            #pragma unroll
            for (int off = 16; off; off >>= 1) {
                const bool hi = (lid & off) != 0;
                #pragma unroll
                for (int k = 0; k < off; k++) {
                    float sent = hi ? v[k] : v[k + off];
                    float recv = __shfl_xor_sync(~0u, sent, off);
                    float keep = hi ? v[k + off] : v[k];
                    v[k] = keep + recv;
                }
            }
            msg[(size_t)node * 256 + c0 + lid] = v[0] * 0.03125f;
        }
        __syncthreads();
    }

    if (wid == 0) {
        asm volatile("tcgen05.relinquish_alloc_permit.cta_group::1.sync.aligned;");
        asm volatile("tcgen05.dealloc.cta_group::1.sync.aligned.b32 %0, 512;" :: "r"(tb));
    }
#else
    // scalar fallback (correct; only used if the sm_103a cubin is absent)
    float* Xf = (float*)smraw;  // [32][260]
    const int tid = threadIdx.x, gb = blockIdx.x;
    for (int nl = 0; nl < 32; nl++) {
        const int node = gb * 32 + nl;
        const int tI = node >> 2, rb = (node & 3) * 32;
        for (int idx = tid; idx < 32 * 256; idx += 256) {
            const int j = idx >> 8, c = idx & 255;
            const int r = rb + j;
            float e = 0.f;
            for (int k = 0; k < 54; k++) {
                float a = __bfloat162float(*(const __nv_bfloat16*)((const char*)efT
                            + (size_t)tI * 16384 + sw128((uint32_t)(r * 128 + k * 2))));
                float w = __bfloat162float(*(const __nv_bfloat16*)((const char*)W1T
                            + sw128((uint32_t)(c * 128 + k * 2))));
                e += a * w;
            }
            e += PiQ[(size_t)node * 256 + c] + PjT[((size_t)(gb * 256 + c)) * 32 + j];
            Xf[j * 260 + c] = silu_f(e);
        }
        __syncthreads();
        const int c = tid;
        float acc = 0.f;
        for (int j = 0; j < 32; j++) {
            float y = b2[c];
            for (int k = 0; k < 256; k++) {
                const size_t byte = (size_t)(k >> 6) * 32768 + (c >> 3) * 1024
                                  + sw128((uint32_t)((c & 7) * 128 + (k & 63) * 2));
                y += Xf[j * 260 + k] * __bfloat162float(*(const __nv_bfloat16*)((const char*)W2T + byte));
            }
            acc += silu_f(y);
        }
        msg[(size_t)node * 256 + c] = acc * (1.0f / 32.0f);
        __syncthreads();
    }
#endif
}

__global__ void graphmean_kernel(const float* __restrict__ h, float* __restrict__ gf)
{
    const int b = blockIdx.x, c = threadIdx.x;
    float s = 0.0f;
    #pragma unroll
    for (int i = 0; i < 32; i++) s += h[(size_t)((b << 5) + i) * HID + c];
    gf[(size_t)b * HID + c] = s * (1.0f / 32.0f);
}

static void run_gemm(cudaStream_t s, const float* A0, int K0, const float* A1, int K1,
                     const float* W, int ldw, const float* bias,
                     float* C, int ldc, int M, int N, int mode)
{
    dim3 grid((M + GBM - 1) / GBM, (N + GBN - 1) / GBN);
    gemm_kernel<<<grid, 256, 0, s>>>(A0, K0, A1, K1, W, ldw, bias, C, ldc, M, N, mode);
}

extern "C" void kernel_launch(void* const* d_in, const int* in_sizes, int n_in,
                              void* d_out, int out_size)
{
    const float* t          = (const float*)d_in[0];
    const float* atom_types = (const float*)d_in[1];
    const float* frac       = (const float*)d_in[2];
    const float* l_polar    = (const float*)d_in[3];
    const float* Ws      = (const float*)d_in[5];
    const float* bs      = (const float*)d_in[6];
    const float* Wn      = (const float*)d_in[7];
    const float* bn      = (const float*)d_in[8];
    const float* ln_g    = (const float*)d_in[9];
    const float* ln_b    = (const float*)d_in[10];
    const float* m1_W    = (const float*)d_in[11];
    const float* m1_b    = (const float*)d_in[12];
    const float* m2_W    = (const float*)d_in[13];
    const float* m2_b    = (const float*)d_in[14];
    const float* a1_W    = (const float*)d_in[15];
    const float* a1_b    = (const float*)d_in[16];
    const float* a2_W    = (const float*)d_in[17];
    const float* a2_b    = (const float*)d_in[18];
    const float* fln_g   = (const float*)d_in[19];
    const float* fln_b   = (const float*)d_in[20];
    const float* type_W  = (const float*)d_in[21];
    const float* type_b  = (const float*)d_in[22];
    const float* polar_W = (const float*)d_in[23];
    const float* frac_W  = (const float*)d_in[24];
    float* out = (float*)d_out;

    float *feat, *nf, *h, *P, *PiQ, *PjT, *msg, *act, *gf;
    __nv_bfloat16 *efT, *W1T, *W2T;
    cudaGetSymbolAddress((void**)&feat, g_feat);
    cudaGetSymbolAddress((void**)&nf,   g_nf);
    cudaGetSymbolAddress((void**)&h,    g_h);
    cudaGetSymbolAddress((void**)&P,    g_P);
    cudaGetSymbolAddress((void**)&PiQ,  g_PiQ);
    cudaGetSymbolAddress((void**)&PjT,  g_PjT);
    cudaGetSymbolAddress((void**)&msg,  g_msg);
    cudaGetSymbolAddress((void**)&act,  g_act);
    cudaGetSymbolAddress((void**)&gf,   g_gf);
    cudaGetSymbolAddress((void**)&efT,  g_efT);
    cudaGetSymbolAddress((void**)&W1T,  g_W1T);
    cudaGetSymbolAddress((void**)&W2T,  g_W2T);

    cudaFuncSetAttribute(edge_msg_tc, cudaFuncAttributeMaxDynamicSharedMemorySize, EDGE_SMEM_REQ);
    cudaStream_t s = 0;

    timefeat_kernel<<<(NODES * 128 + 255) / 256, 256, 0, s>>>(t, feat);
    run_gemm(s, atom_types, TYPED, nullptr, 0, Ws, HID, bs, feat, 384, NODES, HID, 0);
    run_gemm(s, feat, 384, nullptr, 0, Wn, HID, bn, nf, HID, NODES, HID, 0);

    edgefeat_kernel<<<(NTILE * 128 * 64) / 256, 256, 0, s>>>(frac, efT);
    pack_w1t_kernel<<<(NLAY * 256 * 64) / 256, 256, 0, s>>>(m1_W, W1T);
    pack_w2t_kernel<<<(NLAY * 256 * 256) / 256, 256, 0, s>>>(m2_W, W2T);

    for (int l = 0; l < NLAY; l++) {
        const float* W1 = m1_W + (size_t)l * 578 * HID;
        layernorm_kernel<<<NODES, 256, 0, s>>>(nf, ln_g + l * HID, ln_b + l * HID, h);
        run_gemm(s, h, HID, nullptr, 0, W1, HID, m1_b + l * HID, P, 512, NODES, HID, 0);
        run_gemm(s, h, HID, nullptr, 0, W1 + 256 * HID, HID, nullptr, P + 256, 512, NODES, HID, 0);
        prep_kernel<<<NODES, 256, 0, s>>>(P, W1, l_polar, PiQ, PjT);
        edge_msg_tc<<<BGR, 256, EDGE_SMEM_REQ, s>>>(
            PiQ, PjT, efT, W1T + (size_t)l * 16384, W2T + (size_t)l * 65536,
            m2_b + l * HID, msg);
        run_gemm(s, nf, HID, msg, HID, a1_W + (size_t)l * 512 * HID, HID,
                 a1_b + l * HID, act, HID, NODES, HID, 1);
        run_gemm(s, act, HID, nullptr, 0, a2_W + (size_t)l * HID * HID, HID,
                 a2_b + l * HID, nf, HID, NODES, HID, 2);
    }

    layernorm_kernel<<<NODES, 256, 0, s>>>(nf, fln_g, fln_b, h);
    graphmean_kernel<<<BGR, 256, 0, s>>>(h, gf);

    run_gemm(s, h, HID, nullptr, 0, type_W, TYPED, type_b, out, TYPED, NODES, TYPED, 0);
    run_gemm(s, gf, HID, nullptr, 0, polar_W, 6, nullptr, out + (size_t)NODES * TYPED, 6, BGR, 6, 0);
    run_gemm(s, h, HID, nullptr, 0, frac_W, 3, nullptr,
             out + (size_t)NODES * TYPED + (size_t)BGR * 6, 3, NODES, 3, 0);
}